// round 5
// baseline (speedup 1.0000x reference)
#include <cuda_runtime.h>
#include <cuda_fp16.h>
#include <math.h>
#include <stdint.h>

#define D_TOT 2304
#define OUTC  512
#define INC   256
#define HWX   3136          // 56*56
#define NIMG  16
#define NPIX  (NIMG*HWX)    // 50176

#define BK    32
#define NITER (D_TOT/BK)    // 72
#define MT    128           // CTA M tile (channels)
#define NT    128           // CTA N tile (pixels)

#define STAGE_BYTES 16384   // A 8KB + B 8KB per stage
#define NSTAGE 3

// scratch (device globals: no allocation allowed)
__device__ int   g_kidx[OUTC];
__device__ float g_maxrow[D_TOT];
__device__ float g_mul[OUTC];
__device__ int   g_sel[OUTC];
__device__ int   g_active;
__device__ __align__(16) __half g_Wh[(size_t)OUTC * D_TOT];
__device__ __align__(16) __half g_Bh[(size_t)D_TOT * NPIX];   // im2col, pixel-major

// ============================ PTX helpers ====================================
__device__ __forceinline__ uint32_t smem_u32(const void* p) {
    uint32_t a;
    asm("{ .reg .u64 t; cvta.to.shared.u64 t, %1; cvt.u32.u64 %0, t; }"
        : "=r"(a) : "l"(p));
    return a;
}
__device__ __forceinline__ void cp16(uint32_t dst, const void* src) {
    asm volatile("cp.async.cg.shared.global [%0], [%1], 16;"
                 :: "r"(dst), "l"(src) : "memory");
}
#define CP_COMMIT() asm volatile("cp.async.commit_group;" ::: "memory")
#define CP_WAIT(n)  asm volatile("cp.async.wait_group %0;" :: "n"(n) : "memory")

#define LDSM4(r, a)                                                            \
    asm volatile("ldmatrix.sync.aligned.m8n8.x4.shared.b16 {%0,%1,%2,%3}, [%4];" \
        : "=r"((r)[0]), "=r"((r)[1]), "=r"((r)[2]), "=r"((r)[3]) : "r"(a))
#define LDSM4T(r, a)                                                           \
    asm volatile("ldmatrix.sync.aligned.m8n8.x4.trans.shared.b16 {%0,%1,%2,%3}, [%4];" \
        : "=r"((r)[0]), "=r"((r)[1]), "=r"((r)[2]), "=r"((r)[3]) : "r"(a))

__device__ __forceinline__ void mma16(float* c, const uint32_t* a, const uint32_t* b) {
    asm volatile(
        "mma.sync.aligned.m16n8k16.row.col.f32.f16.f16.f32 "
        "{%0,%1,%2,%3}, {%4,%5,%6,%7}, {%8,%9}, {%0,%1,%2,%3};\n"
        : "+f"(c[0]), "+f"(c[1]), "+f"(c[2]), "+f"(c[3])
        : "r"(a[0]), "r"(a[1]), "r"(a[2]), "r"(a[3]), "r"(b[0]), "r"(b[1]));
}

// ============================ small kernels ==================================
__global__ void __launch_bounds__(256) hash_kernels(const float* __restrict__ W,
                                                    const float* __restrict__ a) {
    const int o   = blockIdx.x;
    const int tid = threadIdx.x;
    const float* w = W + (size_t)o * D_TOT;
    float dot = 0.f, n2 = 0.f;
    for (int i = tid; i < D_TOT; i += 256) {
        float v = w[i];
        dot += a[i] * v;
        n2  += v * v;
    }
    __shared__ float s1[256], s2[256];
    s1[tid] = dot; s2[tid] = n2;
    __syncthreads();
    for (int st = 128; st > 0; st >>= 1) {
        if (tid < st) { s1[tid] += s1[tid+st]; s2[tid] += s2[tid+st]; }
        __syncthreads();
    }
    if (tid == 0) {
        float acc = s1[0];
        float pw  = s2[0];
        acc += a[D_TOT+0] * pw; pw *= pw;
        acc += a[D_TOT+1] * pw; pw *= pw;
        acc += a[D_TOT+2] * pw; pw *= pw;
        acc += a[D_TOT+3] * pw; pw *= pw;
        acc += a[D_TOT+4] * pw;
        float h = floorf(acc);
        float r = fmodf(h, 16.f);
        if (r < 0.f) r += 16.f;
        g_kidx[o] = (int)r;
    }
}

__global__ void __launch_bounds__(256) max_rows(const float* __restrict__ x) {
    const int c   = blockIdx.x;
    const int tid = threadIdx.x;
    float m[9];
#pragma unroll
    for (int i = 0; i < 9; i++) m[i] = -1e30f;
    for (int t = tid; t < NIMG * HWX; t += 256) {
        int n = t / HWX;
        int i = t - n * HWX;
        int r = i / 56;
        int s = i - r * 56;
        float v = __ldg(&x[((size_t)n * INC + c) * HWX + i]);
        bool r0 = (r <= 54), r2 = (r >= 1), c0 = (s <= 54), c2 = (s >= 1);
        m[4] = fmaxf(m[4], v);
        if (r0) { m[1] = fmaxf(m[1], v); if (c0) m[0] = fmaxf(m[0], v); if (c2) m[2] = fmaxf(m[2], v); }
        if (c0) m[3] = fmaxf(m[3], v);
        if (c2) m[5] = fmaxf(m[5], v);
        if (r2) { m[7] = fmaxf(m[7], v); if (c0) m[6] = fmaxf(m[6], v); if (c2) m[8] = fmaxf(m[8], v); }
    }
    __shared__ float sred[256];
    for (int q = 0; q < 9; q++) {
        sred[tid] = m[q];
        __syncthreads();
        for (int st = 128; st > 0; st >>= 1) {
            if (tid < st) sred[tid] = fmaxf(sred[tid], sred[tid+st]);
            __syncthreads();
        }
        if (tid == 0) {
            float mv = sred[0];
            if (q != 4) mv = fmaxf(mv, 0.f);
            g_maxrow[q * INC + c] = mv;
        }
        __syncthreads();
    }
}

__global__ void __launch_bounds__(512) build_route(const float* __restrict__ a) {
    const int tid = threadIdx.x;
    __shared__ float red[512];

    float ss = 0.f;
    for (int i = tid; i < D_TOT; i += 512) { float v = g_maxrow[i]; ss += v * v; }
    red[tid] = ss; __syncthreads();
    for (int st = 256; st > 0; st >>= 1) { if (tid < st) red[tid] += red[tid+st]; __syncthreads(); }
    __shared__ float s_norm;
    if (tid == 0) s_norm = sqrtf(red[0]);
    __syncthreads();

    float dot = 0.f;
    for (int i = tid; i < D_TOT; i += 512) dot += a[i] * g_maxrow[i];
    red[tid] = dot; __syncthreads();
    for (int st = 256; st > 0; st >>= 1) { if (tid < st) red[tid] += red[tid+st]; __syncthreads(); }

    __shared__ int s_q, s_cnt, s_pos;
    if (tid == 0) {
        float hs = 0.5f * (a[D_TOT] + a[D_TOT+1] + a[D_TOT+2] + a[D_TOT+3] + a[D_TOT+4]);
        float acc = red[0] / s_norm + hs;
        float h = floorf(acc);
        float r = fmodf(h, 16.f);
        if (r < 0.f) r += 16.f;
        s_q = (int)r;
        s_cnt = 0; s_pos = 0;
    }
    __syncthreads();

    int match = (g_kidx[tid] == s_q) ? 1 : 0;
    if (match) atomicAdd(&s_cnt, 1);
    __syncthreads();
    int count = s_cnt;

    if (count > 0) {
        g_mul[tid] = match ? ((float)OUTC / (float)count) : 0.f;
        if (match) { int pp = atomicAdd(&s_pos, 1); g_sel[pp] = tid; }
        if (tid == 0) g_active = count;
    } else {
        g_mul[tid] = 1.f;
        g_sel[tid] = tid;
        if (tid == 0) g_active = OUTC;
    }
}

__global__ void __launch_bounds__(256) fill_bias(float4* __restrict__ out,
                                                 const float* __restrict__ bias) {
    if (g_active == OUTC) return;   // conv writes every channel in this case
    int i = blockIdx.x * 256 + threadIdx.x;
#pragma unroll
    for (int t = 0; t < 16; t++) {
        int o = (i / 784) & 511;
        float b = __ldg(&bias[o]);
        out[i] = make_float4(b, b, b, b);
        i += 1568 * 256;
    }
}

// W -> half
__global__ void __launch_bounds__(256) w2half(const float* __restrict__ W) {
    int idx = (blockIdx.x * 256 + threadIdx.x) * 4;   // 1152 blocks covers 512*2304
    float4 w = *(const float4*)&W[idx];
    __half2 h0 = __floats2half2_rn(w.x, w.y);
    __half2 h1 = __floats2half2_rn(w.z, w.w);
    uint2 u = make_uint2(*(uint32_t*)&h0, *(uint32_t*)&h1);
    *(uint2*)&g_Wh[idx] = u;
}

// im2col into half, pixel-major rows: g_Bh[k][p], k = tap*256 + c
__global__ void __launch_bounds__(256) im2col_half(const float* __restrict__ x) {
    const int c = blockIdx.y;
    int p0 = blockIdx.x * 2048 + threadIdx.x * 8;
    if (p0 >= NPIX) return;
    const int n   = p0 / HWX;          // all 8 pixels share n (8 | HWX)
    const int rem = p0 - n * HWX;
    const int py  = rem / 56;          // all 8 share py (8 | 56)
    const int px0 = rem - py * 56;
    const float* xc = x + ((size_t)n * INC + c) * HWX;

#pragma unroll
    for (int t9 = 0; t9 < 9; t9++) {
        const int kh = t9 / 3, kw = t9 - 3 * (t9 / 3);
        const int r  = py + kh - 1;
        const int s0 = px0 + kw - 1;
        float v[8];
        if ((unsigned)r < 56u) {
            const float* xr = xc + r * 56;
#pragma unroll
            for (int e = 0; e < 8; e++)
                v[e] = ((unsigned)(s0 + e) < 56u) ? __ldg(&xr[s0 + e]) : 0.f;
        } else {
#pragma unroll
            for (int e = 0; e < 8; e++) v[e] = 0.f;
        }
        __half2 h0 = __floats2half2_rn(v[0], v[1]);
        __half2 h1 = __floats2half2_rn(v[2], v[3]);
        __half2 h2 = __floats2half2_rn(v[4], v[5]);
        __half2 h3 = __floats2half2_rn(v[6], v[7]);
        uint4 u = make_uint4(*(uint32_t*)&h0, *(uint32_t*)&h1,
                             *(uint32_t*)&h2, *(uint32_t*)&h3);
        *(uint4*)&g_Bh[(size_t)(t9 * INC + c) * NPIX + p0] = u;
    }
}

// ============================ tensor-core conv ===============================
// D[m,n] = sum_k A[m,k]*B[n,k]; A from g_Wh (gathered rows), B from g_Bh.
// cp.async 3-stage pipeline; ldmatrix fragment loads; mma m16n8k16 f16.
__global__ void __launch_bounds__(256, 2) conv_mma(const float* __restrict__ bias,
                                                   float* __restrict__ out) {
    const int active = g_active;
    const int mt = blockIdx.x;
    if (mt * MT >= active) return;
    const int nt  = blockIdx.y;
    const int tid = threadIdx.x;
    const int wid  = tid >> 5;
    const int lane = tid & 31;
    const int wm = wid & 1;             // 0..1 (64 rows)
    const int wn = wid >> 1;            // 0..3 (32 cols)

    __shared__ __align__(1024) char smem_raw[NSTAGE * STAGE_BYTES];
    const uint32_t sbase = smem_u32(smem_raw);

    // ---- staging maps ----
    // A: thread -> row aM, two 16B k-chunks (aKc, aKc+1) of the 64B k-row
    const int aM  = tid >> 1;
    const int aKc = (tid & 1) * 2;
    {
    }
    const int gi = mt * MT + aM;
    const int g  = (gi < active) ? g_sel[gi] : 0;
    const __half* asrc = g_Wh + (size_t)g * D_TOT + aKc * 8;
    const uint32_t aSw  = (uint32_t)((aM >> 1) & 3);
    const uint32_t aRow = (uint32_t)((aM >> 1) * 128 + (aM & 1) * 64);
    const uint32_t aDst0 = aRow + (((uint32_t)aKc       ^ aSw) << 4);
    const uint32_t aDst1 = aRow + (((uint32_t)(aKc + 1) ^ aSw) << 4);
    // B: thread -> k-row bK, two 16B n-chunks (bNc, bNc+1)
    const int bK  = tid & 31;
    const int bNc = (tid >> 5) * 2;
    const __half* bsrc = g_Bh + (size_t)bK * NPIX + nt * NT + bNc * 8;
    const uint32_t bRow  = 8192u + (uint32_t)bK * 256u;
    const uint32_t bSw   = (uint32_t)(bK & 7);
    const uint32_t bDst0 = bRow + (((uint32_t)bNc       ^ bSw) << 4);
    const uint32_t bDst1 = bRow + (((uint32_t)(bNc + 1) ^ bSw) << 4);
    const size_t bStep = (size_t)BK * NPIX;   // halfs per iter

    // ---- ldmatrix per-lane offsets (within a stage) ----
    const int q  = lane >> 3;           // matrix id 0..3
    const int r8 = lane & 7;
    uint32_t offA[4][2];
#pragma unroll
    for (int mi = 0; mi < 4; mi++) {
        const int m = wm * 64 + mi * 16 + (q & 1) * 8 + r8;
#pragma unroll
        for (int ks = 0; ks < 2; ks++) {
            const int kc = ks * 2 + (q >> 1);
            offA[mi][ks] = (uint32_t)((m >> 1) * 128 + (m & 1) * 64
                         + ((kc ^ ((m >> 1) & 3)) << 4));
        }
    }
    uint32_t offB[2][2];
#pragma unroll
    for (int pr = 0; pr < 2; pr++) {
        const int nc = wn * 4 + pr * 2 + (q >> 1);
#pragma unroll
        for (int ks = 0; ks < 2; ks++) {
            const int k = ks * 16 + (q & 1) * 8 + r8;
            offB[pr][ks] = 8192u + (uint32_t)(k * 256 + ((nc ^ (k & 7)) << 4));
        }
    }

    // ---- prologue: stage iters 0,1 ----
#pragma unroll
    for (int s = 0; s < 2; s++) {
        const uint32_t base = sbase + s * STAGE_BYTES;
        cp16(base + aDst0, asrc + s * BK);
        cp16(base + aDst1, asrc + s * BK + 8);
        cp16(base + bDst0, bsrc + s * bStep);
        cp16(base + bDst1, bsrc + s * bStep + 8);
        CP_COMMIT();
    }

    float acc[4][4][4];
#pragma unroll
    for (int i = 0; i < 4; i++)
#pragma unroll
        for (int j = 0; j < 4; j++)
#pragma unroll
            for (int r = 0; r < 4; r++) acc[i][j][r] = 0.f;

#pragma unroll 1
    for (int it = 0; it < NITER; it++) {
        if (it + 2 < NITER) CP_WAIT(1); else CP_WAIT(0);
        __syncthreads();

        if (it + 2 < NITER) {
            const int s = (it + 2) % NSTAGE;
            const uint32_t base = sbase + s * STAGE_BYTES;
            cp16(base + aDst0, asrc + (it + 2) * BK);
            cp16(base + aDst1, asrc + (it + 2) * BK + 8);
            cp16(base + bDst0, bsrc + (size_t)(it + 2) * bStep);
            cp16(base + bDst1, bsrc + (size_t)(it + 2) * bStep + 8);
            CP_COMMIT();
        }

        const uint32_t base = sbase + (it % NSTAGE) * STAGE_BYTES;
#pragma unroll
        for (int ks = 0; ks < 2; ks++) {
            uint32_t af[4][4], bf[4][2];
#pragma unroll
            for (int mi = 0; mi < 4; mi++)
                LDSM4(af[mi], base + offA[mi][ks]);
#pragma unroll
            for (int pr = 0; pr < 2; pr++) {
                uint32_t r[4];
                LDSM4T(r, base + offB[pr][ks]);
                bf[2*pr  ][0] = r[0]; bf[2*pr  ][1] = r[1];
                bf[2*pr+1][0] = r[2]; bf[2*pr+1][1] = r[3];
            }
#pragma unroll
            for (int mi = 0; mi < 4; mi++)
#pragma unroll
                for (int nj = 0; nj < 4; nj++)
                    mma16(acc[mi][nj], af[mi], bf[nj]);
        }
    }

    // ---------------- epilogue ----------------
#pragma unroll
    for (int mi = 0; mi < 4; mi++) {
        const int row0 = wm * 64 + mi * 16 + (lane >> 2);
#pragma unroll
        for (int rp = 0; rp < 2; rp++) {
            const int m  = row0 + rp * 8;
            const int gi2 = mt * MT + m;
            if (gi2 >= active) continue;
            const int gg = g_sel[gi2];
            const float mu = g_mul[gg];
            const float bb = __ldg(&bias[gg]);
#pragma unroll
            for (int nj = 0; nj < 4; nj++) {
                const int col = wn * 32 + nj * 8 + 2 * (lane & 3);
                const int pp  = nt * NT + col;
                const int n   = pp / HWX;
                const int rem = pp - n * HWX;
                float2 v;
                v.x = fmaf(mu, acc[mi][nj][rp * 2 + 0], bb);
                v.y = fmaf(mu, acc[mi][nj][rp * 2 + 1], bb);
                *(float2*)&out[((size_t)n * OUTC + gg) * HWX + rem] = v;
            }
        }
    }
}

// ============================================================================
extern "C" void kernel_launch(void* const* d_in, const int* in_sizes, int n_in,
                              void* d_out, int out_size) {
    const float* x = nullptr;
    const float* W = nullptr;
    const float* bias = nullptr;
    const float* a = nullptr;
    for (int i = 0; i < n_in; i++) {
        if (in_sizes[i] == NIMG * INC * HWX)      x    = (const float*)d_in[i];
        else if (in_sizes[i] == OUTC * D_TOT)     W    = (const float*)d_in[i];
        else if (in_sizes[i] == OUTC)             bias = (const float*)d_in[i];
        else if (in_sizes[i] == D_TOT + 5)        a    = (const float*)d_in[i];
    }
    float* out = (float*)d_out;

    hash_kernels<<<OUTC, 256>>>(W, a);
    max_rows<<<INC, 256>>>(x);
    build_route<<<1, 512>>>(a);
    w2half<<<(OUTC * D_TOT) / 1024, 256>>>(W);
    im2col_half<<<dim3(25, INC), 256>>>(x);
    fill_bias<<<1568, 256>>>((float4*)out, bias);
    conv_mma<<<dim3((OUTC + MT - 1) / MT, NPIX / NT), 256>>>(bias, out);
}

// round 6
// speedup vs baseline: 1.3392x; 1.3392x over previous
#include <cuda_runtime.h>
#include <cuda_fp16.h>
#include <math.h>
#include <stdint.h>

#define D_TOT 2304
#define OUTC  512
#define INC   256
#define HWX   3136          // 56*56
#define NIMG  16
#define NPIX  (NIMG*HWX)    // 50176

#define BK    32
#define NITER (D_TOT/BK)    // 72
#define MT    128           // CTA M tile (channels)
#define NT    128           // CTA N tile (pixels)

// B SMEM (u32 units): fragment-ordered packed-half2, double buffered (round 4).
#define B_NSTRIDE 66
#define B_KSTRIDE 1056      // 16*66
#define B_BUF     2112      // 2*1056

// A SMEM: fragment-ordered stream, 2048 u32 per stage, 3 stages (cp.async).
#define A_STAGE_U32 2048

// scratch (device globals: no allocation allowed)
__device__ int   g_kidx[OUTC];
__device__ float g_maxrow[D_TOT];
__device__ float g_mul[OUTC];
__device__ int   g_sel[OUTC];
__device__ int   g_active;
// A fragment stream: [mt(4)][iter(72)][2048 u32]  = 2.36 MB (L2-resident)
__device__ __align__(16) uint32_t g_Wa[4 * NITER * A_STAGE_U32];

// ============================ PTX helpers ====================================
__device__ __forceinline__ uint32_t smem_u32(const void* p) {
    uint32_t a;
    asm("{ .reg .u64 t; cvta.to.shared.u64 t, %1; cvt.u32.u64 %0, t; }"
        : "=r"(a) : "l"(p));
    return a;
}
__device__ __forceinline__ void cp16(uint32_t dst, const void* src) {
    asm volatile("cp.async.cg.shared.global [%0], [%1], 16;"
                 :: "r"(dst), "l"(src) : "memory");
}
#define CP_COMMIT() asm volatile("cp.async.commit_group;" ::: "memory")
#define CP_WAIT(n)  asm volatile("cp.async.wait_group %0;" :: "n"(n) : "memory")

__device__ __forceinline__ uint32_t packh2(float lo, float hi) {
    __half2 h = __floats2half2_rn(lo, hi);
    return *reinterpret_cast<uint32_t*>(&h);
}
__device__ __forceinline__ void mma16(float* c, const uint32_t* a, const uint32_t* b) {
    asm volatile(
        "mma.sync.aligned.m16n8k16.row.col.f32.f16.f16.f32 "
        "{%0,%1,%2,%3}, {%4,%5,%6,%7}, {%8,%9}, {%0,%1,%2,%3};\n"
        : "+f"(c[0]), "+f"(c[1]), "+f"(c[2]), "+f"(c[3])
        : "r"(a[0]), "r"(a[1]), "r"(a[2]), "r"(a[3]), "r"(b[0]), "r"(b[1]));
}

// ============================ small kernels ==================================
__global__ void __launch_bounds__(256) hash_kernels(const float* __restrict__ W,
                                                    const float* __restrict__ a) {
    const int o   = blockIdx.x;
    const int tid = threadIdx.x;
    const float* w = W + (size_t)o * D_TOT;
    float dot = 0.f, n2 = 0.f;
    for (int i = tid; i < D_TOT; i += 256) {
        float v = w[i];
        dot += a[i] * v;
        n2  += v * v;
    }
    __shared__ float s1[256], s2[256];
    s1[tid] = dot; s2[tid] = n2;
    __syncthreads();
    for (int st = 128; st > 0; st >>= 1) {
        if (tid < st) { s1[tid] += s1[tid+st]; s2[tid] += s2[tid+st]; }
        __syncthreads();
    }
    if (tid == 0) {
        float acc = s1[0];
        float pw  = s2[0];
        acc += a[D_TOT+0] * pw; pw *= pw;
        acc += a[D_TOT+1] * pw; pw *= pw;
        acc += a[D_TOT+2] * pw; pw *= pw;
        acc += a[D_TOT+3] * pw; pw *= pw;
        acc += a[D_TOT+4] * pw;
        float h = floorf(acc);
        float r = fmodf(h, 16.f);
        if (r < 0.f) r += 16.f;
        g_kidx[o] = (int)r;
    }
}

__global__ void __launch_bounds__(256) max_rows(const float* __restrict__ x) {
    const int c   = blockIdx.x;
    const int tid = threadIdx.x;
    float m[9];
#pragma unroll
    for (int i = 0; i < 9; i++) m[i] = -1e30f;
    for (int t = tid; t < NIMG * HWX; t += 256) {
        int n = t / HWX;
        int i = t - n * HWX;
        int r = i / 56;
        int s = i - r * 56;
        float v = __ldg(&x[((size_t)n * INC + c) * HWX + i]);
        bool r0 = (r <= 54), r2 = (r >= 1), c0 = (s <= 54), c2 = (s >= 1);
        m[4] = fmaxf(m[4], v);
        if (r0) { m[1] = fmaxf(m[1], v); if (c0) m[0] = fmaxf(m[0], v); if (c2) m[2] = fmaxf(m[2], v); }
        if (c0) m[3] = fmaxf(m[3], v);
        if (c2) m[5] = fmaxf(m[5], v);
        if (r2) { m[7] = fmaxf(m[7], v); if (c0) m[6] = fmaxf(m[6], v); if (c2) m[8] = fmaxf(m[8], v); }
    }
    __shared__ float sred[256];
    for (int q = 0; q < 9; q++) {
        sred[tid] = m[q];
        __syncthreads();
        for (int st = 128; st > 0; st >>= 1) {
            if (tid < st) sred[tid] = fmaxf(sred[tid], sred[tid+st]);
            __syncthreads();
        }
        if (tid == 0) {
            float mv = sred[0];
            if (q != 4) mv = fmaxf(mv, 0.f);
            g_maxrow[q * INC + c] = mv;
        }
        __syncthreads();
    }
}

__global__ void __launch_bounds__(512) build_route(const float* __restrict__ a) {
    const int tid = threadIdx.x;
    __shared__ float red[512];

    float ss = 0.f;
    for (int i = tid; i < D_TOT; i += 512) { float v = g_maxrow[i]; ss += v * v; }
    red[tid] = ss; __syncthreads();
    for (int st = 256; st > 0; st >>= 1) { if (tid < st) red[tid] += red[tid+st]; __syncthreads(); }
    __shared__ float s_norm;
    if (tid == 0) s_norm = sqrtf(red[0]);
    __syncthreads();

    float dot = 0.f;
    for (int i = tid; i < D_TOT; i += 512) dot += a[i] * g_maxrow[i];
    red[tid] = dot; __syncthreads();
    for (int st = 256; st > 0; st >>= 1) { if (tid < st) red[tid] += red[tid+st]; __syncthreads(); }

    __shared__ int s_q, s_cnt, s_pos;
    if (tid == 0) {
        float hs = 0.5f * (a[D_TOT] + a[D_TOT+1] + a[D_TOT+2] + a[D_TOT+3] + a[D_TOT+4]);
        float acc = red[0] / s_norm + hs;
        float h = floorf(acc);
        float r = fmodf(h, 16.f);
        if (r < 0.f) r += 16.f;
        s_q = (int)r;
        s_cnt = 0; s_pos = 0;
    }
    __syncthreads();

    int match = (g_kidx[tid] == s_q) ? 1 : 0;
    if (match) atomicAdd(&s_cnt, 1);
    __syncthreads();
    int count = s_cnt;

    if (count > 0) {
        g_mul[tid] = match ? ((float)OUTC / (float)count) : 0.f;
        if (match) { int pp = atomicAdd(&s_pos, 1); g_sel[pp] = tid; }
        if (tid == 0) g_active = count;
    } else {
        g_mul[tid] = 1.f;
        g_sel[tid] = tid;
        if (tid == 0) g_active = OUTC;
    }
}

__global__ void __launch_bounds__(256) fill_bias(float4* __restrict__ out,
                                                 const float* __restrict__ bias) {
    if (g_active == OUTC) return;   // conv writes every channel in this case
    int i = blockIdx.x * 256 + threadIdx.x;
#pragma unroll
    for (int t = 0; t < 16; t++) {
        int o = (i / 784) & 511;
        float b = __ldg(&bias[o]);
        out[i] = make_float4(b, b, b, b);
        i += 1568 * 256;
    }
}

// Build A fragment stream: g_Wa[mt][it][s], s encodes (kstep, mtile, lane, reg).
// Must run AFTER build_route (uses g_sel / g_active).
__global__ void __launch_bounds__(256) w2frag(const float* __restrict__ W) {
    const int mt  = blockIdx.x;      // 0..3
    const int it  = blockIdx.y;      // 0..71
    const int tid = threadIdx.x;
    const int active = g_active;
    uint32_t v[8];
#pragma unroll
    for (int j = 0; j < 8; j++) {
        int s     = tid * 8 + j;
        int kstep = s >> 10;
        int mtile = (s >> 7) & 7;
        int lane  = (s >> 2) & 31;
        int reg   = s & 3;
        int m  = mtile * 16 + (lane >> 2) + (reg & 1) * 8;
        int kl = kstep * 16 + (lane & 3) * 2 + ((reg >> 1) & 1) * 8;
        int k  = it * 32 + kl;
        int gi = mt * MT + m;
        int g  = (gi < active) ? g_sel[gi] : 0;
        float2 w2 = __ldg((const float2*)&W[(size_t)g * D_TOT + k]);
        v[j] = packh2(w2.x, w2.y);
    }
    uint32_t* dst = g_Wa + ((size_t)(mt * NITER + it)) * A_STAGE_U32 + tid * 8;
    *(uint4*)dst       = make_uint4(v[0], v[1], v[2], v[3]);
    *(uint4*)(dst + 4) = make_uint4(v[4], v[5], v[6], v[7]);
}

// ============================ tensor-core conv ===============================
// D[m,n] = sum_k A[m,k]*B[n,k]; A from g_Wa fragment stream via cp.async,
// B built on the fly from L2-resident x (round-4 staging).
__global__ void __launch_bounds__(256, 2) conv_mma(const float* __restrict__ x,
                                                   const float* __restrict__ bias,
                                                   float* __restrict__ out) {
    const int active = g_active;
    const int mt = blockIdx.x;
    if (mt * MT >= active) return;
    const int nt  = blockIdx.y;
    const int tid = threadIdx.x;
    const int wid  = tid >> 5;
    const int lane = tid & 31;
    const int wm = wid & 1;             // 0..1 (64 rows)
    const int wn = wid >> 1;            // 0..3 (32 cols)

    __shared__ __align__(16) uint32_t smA[3 * A_STAGE_U32];
    __shared__ uint32_t smB[2 * B_BUF];

    const uint32_t sA = smem_u32(smA);
    const uint32_t* aSrc = g_Wa + (size_t)mt * NITER * A_STAGE_U32;
    const uint32_t aDstOff = (uint32_t)tid * 32;   // bytes

    // ---- B staging: thread (np, kh): pixel np, kstep kh, 8 k-pairs ----
    const int np = tid & 127;
    const int kh = tid >> 7;            // 0/1
    const int p  = nt * NT + np;
    const int pn = p / HWX;
    const int prem = p - pn * HWX;
    const int py = prem / 56;
    const int px = prem - py * 56;
    const float* xb = x + (size_t)pn * INC * HWX;
    const int b_base = kh * B_KSTRIDE + (np >> 3) * B_NSTRIDE + (np & 7) * 8;

    uint32_t bP[8];

    // ---------------- prologue ----------------
    // A: cp.async stages 0 and 1
#pragma unroll
    for (int s = 0; s < 2; s++) {
        const uint32_t d = sA + (uint32_t)s * (A_STAGE_U32 * 4) + aDstOff;
        const uint32_t* src = aSrc + s * A_STAGE_U32 + tid * 8;
        cp16(d, src);
        cp16(d + 16, src + 4);
        CP_COMMIT();
    }
    // B chunk 0 -> buf 0
    {
        const int r = py - 1, s = px - 1;      // tap (0,0)
        const bool ok = ((unsigned)r < 56u) && ((unsigned)s < 56u);
        const float* bp = xb + (size_t)(kh * 16) * HWX + r * 56 + s;
#pragma unroll
        for (int j = 0; j < 8; j++) {
            float v0 = ok ? __ldg(bp + (2*j) * HWX)   : 0.f;
            float v1 = ok ? __ldg(bp + (2*j+1) * HWX) : 0.f;
            bP[j] = packh2(v0, v1);
        }
#pragma unroll
        for (int j = 0; j < 8; j++) smB[b_base + (j & 3) * 2 + (j >> 2)] = bP[j];
    }

    float acc[4][4][4];
#pragma unroll
    for (int i = 0; i < 4; i++)
#pragma unroll
        for (int j = 0; j < 4; j++)
#pragma unroll
            for (int r = 0; r < 4; r++) acc[i][j][r] = 0.f;

#pragma unroll 1
    for (int it = 0; it < NITER; it++) {
        // ---- prefetch next B chunk to regs ----
        if (it + 1 < NITER) {
            const int k0 = (it + 1) * BK;
            const int t9 = k0 >> 8;
            const int khh = (t9 * 11) >> 5;     // t9/3
            const int kww = t9 - 3 * khh;
            const int r  = py + khh - 1;
            const int s  = px + kww - 1;
            const bool ok = ((unsigned)r < 56u) && ((unsigned)s < 56u);
            const float* bp = xb + (size_t)((k0 & 255) + kh * 16) * HWX + r * 56 + s;
#pragma unroll
            for (int j = 0; j < 8; j++) {
                float v0 = ok ? __ldg(bp + (2*j) * HWX)   : 0.f;
                float v1 = ok ? __ldg(bp + (2*j+1) * HWX) : 0.f;
                bP[j] = packh2(v0, v1);
            }
        }

        // ---- own A(it) copies done, then make everything visible ----
        if (it + 1 < NITER) CP_WAIT(1); else CP_WAIT(0);
        __syncthreads();

        // ---- issue A(it+2) into the stage freed by iter it-1 ----
        if (it + 2 < NITER) {
            const int st = (it + 2) % 3;
            const uint32_t d = sA + (uint32_t)st * (A_STAGE_U32 * 4) + aDstOff;
            const uint32_t* src = aSrc + (it + 2) * A_STAGE_U32 + tid * 8;
            cp16(d, src);
            cp16(d + 16, src + 4);
            CP_COMMIT();
        }

        // ---- compute ----
        const uint32_t aoff = (uint32_t)(it % 3) * A_STAGE_U32;
        const uint32_t boff = (uint32_t)(it & 1) * B_BUF;
#pragma unroll
        for (int ks = 0; ks < 2; ks++) {
            uint32_t af[4][4], bf[4][2];
#pragma unroll
            for (int j = 0; j < 4; j++) {
                uint4 v = *(const uint4*)&smA[aoff + ks * 1024
                                              + (wm * 4 + j) * 128 + lane * 4];
                af[j][0] = v.x; af[j][1] = v.y; af[j][2] = v.z; af[j][3] = v.w;
            }
#pragma unroll
            for (int j = 0; j < 4; j++) {
                uint2 v = *(const uint2*)&smB[boff + ks * B_KSTRIDE
                                              + (wn * 4 + j) * B_NSTRIDE + lane * 2];
                bf[j][0] = v.x; bf[j][1] = v.y;
            }
#pragma unroll
            for (int mi = 0; mi < 4; mi++)
#pragma unroll
                for (int nj = 0; nj < 4; nj++)
                    mma16(acc[mi][nj], af[mi], bf[nj]);
        }

        // ---- store next B chunk into other buffer ----
        if (it + 1 < NITER) {
            const uint32_t nb = (uint32_t)((it + 1) & 1) * B_BUF;
#pragma unroll
            for (int j = 0; j < 8; j++)
                smB[nb + b_base + (j & 3) * 2 + (j >> 2)] = bP[j];
        }
    }

    // ---------------- epilogue ----------------
#pragma unroll
    for (int mi = 0; mi < 4; mi++) {
        const int row0 = wm * 64 + mi * 16 + (lane >> 2);
#pragma unroll
        for (int rp = 0; rp < 2; rp++) {
            const int m  = row0 + rp * 8;
            const int gi = mt * MT + m;
            if (gi >= active) continue;
            const int g  = g_sel[gi];
            const float mu = g_mul[g];
            const float bb = __ldg(&bias[g]);
#pragma unroll
            for (int nj = 0; nj < 4; nj++) {
                const int col = wn * 32 + nj * 8 + 2 * (lane & 3);
                const int pp  = nt * NT + col;
                const int n   = pp / HWX;
                const int rem = pp - n * HWX;
                float2 v;
                v.x = fmaf(mu, acc[mi][nj][rp * 2 + 0], bb);
                v.y = fmaf(mu, acc[mi][nj][rp * 2 + 1], bb);
                *(float2*)&out[((size_t)n * OUTC + g) * HWX + rem] = v;
            }
        }
    }
}

// ============================================================================
extern "C" void kernel_launch(void* const* d_in, const int* in_sizes, int n_in,
                              void* d_out, int out_size) {
    const float* x = nullptr;
    const float* W = nullptr;
    const float* bias = nullptr;
    const float* a = nullptr;
    for (int i = 0; i < n_in; i++) {
        if (in_sizes[i] == NIMG * INC * HWX)      x    = (const float*)d_in[i];
        else if (in_sizes[i] == OUTC * D_TOT)     W    = (const float*)d_in[i];
        else if (in_sizes[i] == OUTC)             bias = (const float*)d_in[i];
        else if (in_sizes[i] == D_TOT + 5)        a    = (const float*)d_in[i];
    }
    float* out = (float*)d_out;

    hash_kernels<<<OUTC, 256>>>(W, a);
    max_rows<<<INC, 256>>>(x);
    build_route<<<1, 512>>>(a);
    w2frag<<<dim3(4, NITER), 256>>>(W);
    fill_bias<<<1568, 256>>>((float4*)out, bias);
    conv_mma<<<dim3((OUTC + MT - 1) / MT, NPIX / NT), 256>>>(x, bias, out);
}